// round 5
// baseline (speedup 1.0000x reference)
#include <cuda_runtime.h>
#include <cuda_fp16.h>
#include <math.h>

#define NN 100000
#define NE 3200000
#define EK_BLOCKS 3125
#define EK_ITER   8     // 3125 blocks * 8 warps * 16 edges * 8 iters = 3.2M

// Scratch (device globals; zero-init at load; every invocation restores zeros
// => deterministic under graph replay)
__device__ float    g_deg[NN];
__device__ double   g_sum;
__device__ unsigned g_done;
__device__ __align__(16) __half g_ynorm[NN * 16];   // y * rsqrt(degree), 32B/row

// Per-warp dtype detect: int64 < 100000 => odd 32-bit words all zero.
__device__ __forceinline__ int detect_is64(const void* ei) {
    int lane = threadIdx.x & 31;
    unsigned v = ((const unsigned*)ei)[2 * lane + 1];
    return __ballot_sync(0xffffffffu, v == 0u) == 0xffffffffu;
}

// ---------------------------------------------------------------------------
// Kernel 1: degree = segment_sum(edge_weights, row). g_deg arrives zeroed.
// ---------------------------------------------------------------------------
__global__ void degree_kernel(const void* __restrict__ ei,
                              const float4* __restrict__ w4) {
    int is64 = detect_is64(ei);
    int t = blockIdx.x * blockDim.x + threadIdx.x;   // grid = NE/4 threads
    float4 w = w4[t];
    int r0, r1, r2, r3;
    if (is64) {
        const longlong2* p = (const longlong2*)ei;
        longlong2 a = p[2 * t], b = p[2 * t + 1];
        r0 = (int)a.x; r1 = (int)a.y; r2 = (int)b.x; r3 = (int)b.y;
    } else {
        int4 a = ((const int4*)ei)[t];
        r0 = a.x; r1 = a.y; r2 = a.z; r3 = a.w;
    }
    atomicAdd(&g_deg[r0], w.x);
    atomicAdd(&g_deg[r1], w.y);
    atomicAdd(&g_deg[r2], w.z);
    atomicAdd(&g_deg[r3], w.w);
}

// ---------------------------------------------------------------------------
// Kernel 2: ynorm[n] = y[n] * rsqrt(degree[n]) in fp16; re-zero g_deg.
// ---------------------------------------------------------------------------
__global__ void ynorm_kernel(const float4* __restrict__ y) {
    int i = blockIdx.x * blockDim.x + threadIdx.x;
    if (i >= NN) return;
    float dinv = rsqrtf(g_deg[i]);
    g_deg[i] = 0.0f;                                  // restore invariant
    __half2* out = (__half2*)(g_ynorm + (size_t)i * 16);
    #pragma unroll
    for (int k = 0; k < 4; k++) {
        float4 v = y[i * 4 + k];
        out[2 * k]     = __floats2half2_rn(v.x * dinv, v.y * dinv);
        out[2 * k + 1] = __floats2half2_rn(v.z * dinv, v.w * dinv);
    }
}

// Forced-in-flight 16B gather: volatile asm cannot be sunk into compute.
__device__ __forceinline__ uint4 ldg_v4(const uint4* p) {
    uint4 v;
    asm volatile("ld.global.nc.v4.u32 {%0,%1,%2,%3}, [%4];"
                 : "=r"(v.x), "=r"(v.y), "=r"(v.z), "=r"(v.w)
                 : "l"(p));
    return v;
}

// ---------------------------------------------------------------------------
// Kernel 3: per-edge weighted L2 of ynorm[r]-ynorm[c] -> mean in d_out.
// 2 lanes per edge (16B each of the 32B row). All 16 gathers forced into
// flight via volatile asm before any compute. Last block finalizes.
// ---------------------------------------------------------------------------
__global__ void __launch_bounds__(256, 2)
edge_kernel(const void* __restrict__ ei, const float* __restrict__ w,
            float* __restrict__ out) {
    int is64   = detect_is64(ei);
    int tid    = blockIdx.x * blockDim.x + threadIdx.x;
    int warpId = tid >> 5;
    int lane   = threadIdx.x & 31;
    int gid    = lane >> 1;      // edge slot within the warp's 16
    int sub    = lane & 1;       // which 16B half of the 32B row
    int base   = warpId * (16 * EK_ITER);
    const uint4* yn = (const uint4*)g_ynorm;

    // Phase 1: indices + weights (coalesced)
    int r[EK_ITER], c[EK_ITER];
    float wv[EK_ITER];
    if (is64) {
        const long long* p = (const long long*)ei;
        #pragma unroll
        for (int j = 0; j < EK_ITER; j++) {
            int e = base + j * 16 + gid;
            r[j] = (int)p[e];
            c[j] = (int)p[NE + e];
        }
    } else {
        const int* p = (const int*)ei;
        #pragma unroll
        for (int j = 0; j < EK_ITER; j++) {
            int e = base + j * 16 + gid;
            r[j] = p[e];
            c[j] = p[NE + e];
        }
    }
    #pragma unroll
    for (int j = 0; j < EK_ITER; j++) wv[j] = w[base + j * 16 + gid];

    // Phase 2: all 16 gathers issued back-to-back (cannot be sunk)
    uint4 hr[EK_ITER], hc[EK_ITER];
    #pragma unroll
    for (int j = 0; j < EK_ITER; j++) {
        hr[j] = ldg_v4(yn + (r[j] * 2 + sub));
        hc[j] = ldg_v4(yn + (c[j] * 2 + sub));
    }

    // Phase 3: compute
    float acc = 0.0f;
    #pragma unroll
    for (int j = 0; j < EK_ITER; j++) {
        float s = 0.0f;
        const __half2* a2 = (const __half2*)&hr[j];
        const __half2* b2 = (const __half2*)&hc[j];
        #pragma unroll
        for (int k = 0; k < 4; k++) {
            float2 a = __half22float2(a2[k]);
            float2 b = __half22float2(b2[k]);
            float d0 = a.x - b.x;
            float d1 = a.y - b.y;
            s += d0 * d0 + d1 * d1;
        }
        s += __shfl_xor_sync(0xffffffffu, s, 1);
        if (sub == 0) acc += sqrtf(s) * wv[j];
    }

    // Block reduction
    #pragma unroll
    for (int off = 16; off; off >>= 1)
        acc += __shfl_down_sync(0xffffffffu, acc, off);
    __shared__ float warp_sums[8];
    int wid = threadIdx.x >> 5;
    if (lane == 0) warp_sums[wid] = acc;
    __syncthreads();
    if (wid == 0) {
        float v = (lane < 8) ? warp_sums[lane] : 0.0f;
        #pragma unroll
        for (int off = 4; off; off >>= 1)
            v += __shfl_down_sync(0xffffffffu, v, off);
        if (lane == 0) {
            atomicAdd(&g_sum, (double)v);
            __threadfence();
            unsigned ticket = atomicAdd(&g_done, 1u);
            if (ticket == EK_BLOCKS - 1) {            // last block: finalize
                out[0] = (float)(g_sum / (double)NE);
                g_sum  = 0.0;                          // restore invariants
                g_done = 0u;
                __threadfence();
            }
        }
    }
}

extern "C" void kernel_launch(void* const* d_in, const int* in_sizes, int n_in,
                              void* d_out, int out_size) {
    const void*  ei = d_in[0];                  // edge_index (2, NE)
    const float* w  = (const float*)d_in[1];    // edge_weights (NE,)
    const float* y  = (const float*)d_in[2];    // y (NN, 16)

    degree_kernel<<<NE / 4 / 256, 256>>>(ei, (const float4*)w);
    ynorm_kernel<<<(NN + 255) / 256, 256>>>((const float4*)y);
    edge_kernel<<<EK_BLOCKS, 256>>>(ei, w, (float*)d_out);
}

// round 6
// speedup vs baseline: 1.2474x; 1.2474x over previous
#include <cuda_runtime.h>
#include <cuda_fp16.h>
#include <math.h>

#define NN 100000
#define NE 3200000
#define EK_BLOCKS 3125
#define EK_ITER   8     // 3125 blocks * 8 warps * 16 edges * 8 iters = 3.2M

// Scratch (device globals; zero-init at load; every invocation restores zeros
// => deterministic under graph replay)
__device__ float    g_deg[NN];
__device__ double   g_sum;
__device__ unsigned g_done;
__device__ __align__(16) __half g_ynorm[NN * 16];   // y * rsqrt(degree), 32B/row

// Per-warp dtype detect: int64 < 100000 => odd 32-bit words all zero.
__device__ __forceinline__ int detect_is64(const void* ei) {
    int lane = threadIdx.x & 31;
    unsigned v = ((const unsigned*)ei)[2 * lane + 1];
    return __ballot_sync(0xffffffffu, v == 0u) == 0xffffffffu;
}

// ---------------------------------------------------------------------------
// Kernel 1: degree = segment_sum(edge_weights, row). 2 edges/thread.
// ---------------------------------------------------------------------------
__global__ void degree_kernel(const void* __restrict__ ei,
                              const float2* __restrict__ w2) {
    int is64 = detect_is64(ei);
    int t = blockIdx.x * blockDim.x + threadIdx.x;   // grid = NE/2 threads
    float2 w = w2[t];
    int r0, r1;
    if (is64) {
        longlong2 a = ((const longlong2*)ei)[t];
        r0 = (int)a.x; r1 = (int)a.y;
    } else {
        int2 a = ((const int2*)ei)[t];
        r0 = a.x; r1 = a.y;
    }
    atomicAdd(&g_deg[r0], w.x);
    atomicAdd(&g_deg[r1], w.y);
}

// ---------------------------------------------------------------------------
// Kernel 2: ynorm[n] = y[n] * rsqrt(degree[n]) in fp16; re-zero g_deg.
// ---------------------------------------------------------------------------
__global__ void ynorm_kernel(const float4* __restrict__ y) {
    int i = blockIdx.x * blockDim.x + threadIdx.x;
    if (i >= NN) return;
    float dinv = rsqrtf(g_deg[i]);
    g_deg[i] = 0.0f;                                  // restore invariant
    __half2* out = (__half2*)(g_ynorm + (size_t)i * 16);
    #pragma unroll
    for (int k = 0; k < 4; k++) {
        float4 v = y[i * 4 + k];
        out[2 * k]     = __floats2half2_rn(v.x * dinv, v.y * dinv);
        out[2 * k + 1] = __floats2half2_rn(v.z * dinv, v.w * dinv);
    }
}

// ---------------------------------------------------------------------------
// Kernel 3: per-edge weighted L2 of ynorm[r]-ynorm[c] -> mean in d_out.
// 2 lanes per edge (16B each of the 32B row), compiler-scheduled loop
// (measured best form). Last block finalizes in-kernel.
// ---------------------------------------------------------------------------
__global__ void __launch_bounds__(256)
edge_kernel(const void* __restrict__ ei, const float* __restrict__ w,
            float* __restrict__ out) {
    int is64   = detect_is64(ei);
    int tid    = blockIdx.x * blockDim.x + threadIdx.x;
    int warpId = tid >> 5;
    int lane   = threadIdx.x & 31;
    int gid    = lane >> 1;      // edge slot within the warp's 16
    int sub    = lane & 1;       // which 16B half of the 32B row
    int base   = warpId * (16 * EK_ITER);
    const uint4* yn = (const uint4*)g_ynorm;

    float acc = 0.0f;
    #pragma unroll 4
    for (int j = 0; j < EK_ITER; j++) {
        int e = base + j * 16 + gid;
        int r, c;
        if (is64) {
            const long long* p = (const long long*)ei;
            r = (int)p[e];
            c = (int)p[NE + e];
        } else {
            const int* p = (const int*)ei;
            r = p[e];
            c = p[NE + e];
        }
        float we = w[e];
        uint4 hr = yn[r * 2 + sub];
        uint4 hc = yn[c * 2 + sub];

        float s = 0.0f;
        const __half2* a2 = (const __half2*)&hr;
        const __half2* b2 = (const __half2*)&hc;
        #pragma unroll
        for (int k = 0; k < 4; k++) {
            float2 a = __half22float2(a2[k]);
            float2 b = __half22float2(b2[k]);
            float d0 = a.x - b.x;
            float d1 = a.y - b.y;
            s += d0 * d0 + d1 * d1;
        }
        s += __shfl_xor_sync(0xffffffffu, s, 1);
        if (sub == 0) acc += sqrtf(s) * we;
    }

    // Block reduction
    #pragma unroll
    for (int off = 16; off; off >>= 1)
        acc += __shfl_down_sync(0xffffffffu, acc, off);
    __shared__ float warp_sums[8];
    int wid = threadIdx.x >> 5;
    if (lane == 0) warp_sums[wid] = acc;
    __syncthreads();
    if (wid == 0) {
        float v = (lane < 8) ? warp_sums[lane] : 0.0f;
        #pragma unroll
        for (int off = 4; off; off >>= 1)
            v += __shfl_down_sync(0xffffffffu, v, off);
        if (lane == 0) {
            atomicAdd(&g_sum, (double)v);
            __threadfence();
            unsigned ticket = atomicAdd(&g_done, 1u);
            if (ticket == EK_BLOCKS - 1) {            // last block: finalize
                out[0] = (float)(g_sum / (double)NE);
                g_sum  = 0.0;                          // restore invariants
                g_done = 0u;
                __threadfence();
            }
        }
    }
}

extern "C" void kernel_launch(void* const* d_in, const int* in_sizes, int n_in,
                              void* d_out, int out_size) {
    const void*  ei = d_in[0];                  // edge_index (2, NE)
    const float* w  = (const float*)d_in[1];    // edge_weights (NE,)
    const float* y  = (const float*)d_in[2];    // y (NN, 16)

    degree_kernel<<<NE / 2 / 256, 256>>>(ei, (const float2*)w);
    ynorm_kernel<<<(NN + 255) / 256, 256>>>((const float4*)y);
    edge_kernel<<<EK_BLOCKS, 256>>>(ei, w, (float*)d_out);
}

// round 7
// speedup vs baseline: 1.2833x; 1.0288x over previous
#include <cuda_runtime.h>
#include <cuda_fp16.h>
#include <math.h>

#define NN 100000
#define NE 3200000
#define EK_BLOCKS 3125   // 3125 blocks * 8 warps * 128 edges/warp = 3.2M

// Scratch (device globals; zero-init at load; every invocation restores zeros
// => deterministic under graph replay)
__device__ float    g_deg[NN];
__device__ double   g_sum;
__device__ unsigned g_done;
__device__ __align__(16) __half g_ynorm[NN * 16];   // y * rsqrt(degree), 32B/row

// Per-warp dtype detect: int64 < 100000 => odd 32-bit words all zero.
__device__ __forceinline__ int detect_is64(const void* ei) {
    int lane = threadIdx.x & 31;
    unsigned v = ((const unsigned*)ei)[2 * lane + 1];
    return __ballot_sync(0xffffffffu, v == 0u) == 0xffffffffu;
}

// ---------------------------------------------------------------------------
// Kernel 1: degree = segment_sum(edge_weights, row). 2 edges/thread.
// ---------------------------------------------------------------------------
__global__ void degree_kernel(const void* __restrict__ ei,
                              const float2* __restrict__ w2) {
    int is64 = detect_is64(ei);
    int t = blockIdx.x * blockDim.x + threadIdx.x;   // grid = NE/2 threads
    float2 w = w2[t];
    int r0, r1;
    if (is64) {
        longlong2 a = ((const longlong2*)ei)[t];
        r0 = (int)a.x; r1 = (int)a.y;
    } else {
        int2 a = ((const int2*)ei)[t];
        r0 = a.x; r1 = a.y;
    }
    atomicAdd(&g_deg[r0], w.x);
    atomicAdd(&g_deg[r1], w.y);
}

// ---------------------------------------------------------------------------
// Kernel 2: ynorm[n] = y[n] * rsqrt(degree[n]) in fp16; re-zero g_deg.
// ---------------------------------------------------------------------------
__global__ void ynorm_kernel(const float4* __restrict__ y) {
    int i = blockIdx.x * blockDim.x + threadIdx.x;
    if (i >= NN) return;
    float dinv = rsqrtf(g_deg[i]);
    g_deg[i] = 0.0f;                                  // restore invariant
    __half2* out = (__half2*)(g_ynorm + (size_t)i * 16);
    #pragma unroll
    for (int k = 0; k < 4; k++) {
        float4 v = y[i * 4 + k];
        out[2 * k]     = __floats2half2_rn(v.x * dinv, v.y * dinv);
        out[2 * k + 1] = __floats2half2_rn(v.z * dinv, v.w * dinv);
    }
}

// ---------------------------------------------------------------------------
// Kernel 3: per-edge weighted L2 of ynorm[r]-ynorm[c] -> mean in d_out.
// Lane pair (gid, sub) owns 8 CONSECUTIVE edges; indices/weights load as
// vectors (longlong2/int4/float4); diff+square-accumulate in half2
// (HSUB2/HFMA2); sqrt lane alternates per edge. Last block finalizes.
// ---------------------------------------------------------------------------
__global__ void __launch_bounds__(256)
edge_kernel(const void* __restrict__ ei, const float* __restrict__ w,
            float* __restrict__ out) {
    int is64   = detect_is64(ei);
    int tid    = blockIdx.x * blockDim.x + threadIdx.x;
    int warpId = tid >> 5;
    int lane   = threadIdx.x & 31;
    int gid    = lane >> 1;      // edge-group slot (16 per warp)
    int sub    = lane & 1;       // which 16B half of the 32B row
    int e0     = warpId * 128 + gid * 8;   // this lane's 8 consecutive edges
    const uint4* yn = (const uint4*)g_ynorm;

    // Vectorized index + weight loads for 8 edges
    int r[8], c[8];
    if (is64) {
        const longlong2* pr = (const longlong2*)ei + (e0 >> 1);
        const longlong2* pc = (const longlong2*)ei + ((NE + e0) >> 1);
        #pragma unroll
        for (int k = 0; k < 4; k++) {
            longlong2 a = pr[k];
            longlong2 b = pc[k];
            r[2 * k] = (int)a.x; r[2 * k + 1] = (int)a.y;
            c[2 * k] = (int)b.x; c[2 * k + 1] = (int)b.y;
        }
    } else {
        const int4* pr = (const int4*)ei + (e0 >> 2);
        const int4* pc = (const int4*)ei + ((NE + e0) >> 2);
        #pragma unroll
        for (int k = 0; k < 2; k++) {
            int4 a = pr[k];
            int4 b = pc[k];
            r[4 * k] = a.x; r[4 * k + 1] = a.y; r[4 * k + 2] = a.z; r[4 * k + 3] = a.w;
            c[4 * k] = b.x; c[4 * k + 1] = b.y; c[4 * k + 2] = b.z; c[4 * k + 3] = b.w;
        }
    }
    float wv[8];
    {
        const float4* pw = (const float4*)(w + e0);
        float4 w0 = pw[0], w1 = pw[1];
        wv[0] = w0.x; wv[1] = w0.y; wv[2] = w0.z; wv[3] = w0.w;
        wv[4] = w1.x; wv[5] = w1.y; wv[6] = w1.z; wv[7] = w1.w;
    }

    float acc = 0.0f;
    #pragma unroll
    for (int j = 0; j < 8; j++) {
        uint4 hr = yn[r[j] * 2 + sub];
        uint4 hc = yn[c[j] * 2 + sub];
        const __half2* a2 = (const __half2*)&hr;
        const __half2* b2 = (const __half2*)&hc;
        __half2 s2 = __float2half2_rn(0.0f);
        #pragma unroll
        for (int k = 0; k < 4; k++) {
            __half2 d = __hsub2(a2[k], b2[k]);
            s2 = __hfma2(d, d, s2);
        }
        float s = __low2float(s2) + __high2float(s2);
        s += __shfl_xor_sync(0xffffffffu, s, 1);
        if (sub == (j & 1)) acc += sqrtf(s) * wv[j];
    }

    // Block reduction
    #pragma unroll
    for (int off = 16; off; off >>= 1)
        acc += __shfl_down_sync(0xffffffffu, acc, off);
    __shared__ float warp_sums[8];
    int wid = threadIdx.x >> 5;
    if (lane == 0) warp_sums[wid] = acc;
    __syncthreads();
    if (wid == 0) {
        float v = (lane < 8) ? warp_sums[lane] : 0.0f;
        #pragma unroll
        for (int off = 4; off; off >>= 1)
            v += __shfl_down_sync(0xffffffffu, v, off);
        if (lane == 0) {
            atomicAdd(&g_sum, (double)v);
            __threadfence();
            unsigned ticket = atomicAdd(&g_done, 1u);
            if (ticket == EK_BLOCKS - 1) {            // last block: finalize
                out[0] = (float)(g_sum / (double)NE);
                g_sum  = 0.0;                          // restore invariants
                g_done = 0u;
                __threadfence();
            }
        }
    }
}

extern "C" void kernel_launch(void* const* d_in, const int* in_sizes, int n_in,
                              void* d_out, int out_size) {
    const void*  ei = d_in[0];                  // edge_index (2, NE)
    const float* w  = (const float*)d_in[1];    // edge_weights (NE,)
    const float* y  = (const float*)d_in[2];    // y (NN, 16)

    degree_kernel<<<NE / 2 / 256, 256>>>(ei, (const float2*)w);
    ynorm_kernel<<<(NN + 255) / 256, 256>>>((const float4*)y);
    edge_kernel<<<EK_BLOCKS, 256>>>(ei, w, (float*)d_out);
}